// round 2
// baseline (speedup 1.0000x reference)
#include <cuda_runtime.h>

// CLinear: out[M,N] = x[M,K] @ dequant(packed, mn, scale)[N,K]^T + bias[N]
// M = 8192 (4*2048), N = 4096, K = 4096, group size 64 along K.
// packed: [N, 64 groups, 32] int32, each int holds one byte; hi nibble = first
// half of group (k_local 0..31), lo nibble = second half (k_local 32..63).
// w[n, g*64 + h*32 + j] = nibble / scale[n,g] + mn[n,g]

#define BM 128
#define BN 128
#define BK 32
#define TM 8
#define TN 8
#define NTHREADS 256
#define XS_LD 36    // xs row stride (floats): BK + 4 pad, 16B-aligned rows
#define WS_LD 132   // ws row stride (floats): BN + 4 pad, 16B-aligned rows
#define K_DIM 4096
#define N_DIM 4096
#define NUM_GROUPS 64

__global__ __launch_bounds__(NTHREADS, 2)
void clinear_kernel(const float* __restrict__ x,
                    const int*   __restrict__ packed,
                    const float* __restrict__ mn,
                    const float* __restrict__ scale,
                    const float* __restrict__ bias,
                    float* __restrict__ out) {
    __shared__ float xs[BM * XS_LD];   // [m][k] natural layout
    __shared__ float ws[BK * WS_LD];   // [k][n] transposed (dequantized W)

    const int tid = threadIdx.x;
    const int n0 = blockIdx.x * BN;
    const int m0 = blockIdx.y * BM;
    const int tx = tid & 15;          // 16 thread cols -> n
    const int ty = tid >> 4;          // 16 thread rows -> m

    float acc[TM][TN];
#pragma unroll
    for (int i = 0; i < TM; i++)
#pragma unroll
        for (int j = 0; j < TN; j++) acc[i][j] = 0.0f;

    for (int kt = 0; kt < K_DIM / BK; kt++) {
        const int g = kt >> 1;      // quant group index
        const int h = kt & 1;       // 0: hi nibble half, 1: lo nibble half

        // ---- load x tile [BM][BK] (coalesced: 8 lanes cover one 128B row) ----
#pragma unroll
        for (int i = 0; i < 4; i++) {
            int s  = tid + i * NTHREADS;    // 1024 float4 slots
            int m  = s >> 3;                // 0..127
            int c4 = s & 7;                 // 0..7 (float4 within row)
            float4 v = *reinterpret_cast<const float4*>(
                x + (size_t)(m0 + m) * K_DIM + (size_t)kt * BK + c4 * 4);
            *reinterpret_cast<float4*>(&xs[m * XS_LD + c4 * 4]) = v;
        }

        // ---- load + dequantize W tile -> ws[k][n] ----
        // 128 n-rows x 8 int4 slots (32 ints/row). Each int4 -> 4 nibbles -> 4 k.
#pragma unroll
        for (int i = 0; i < 4; i++) {
            int s   = tid + i * NTHREADS;   // 1024 int4 slots
            int n_l = s >> 3;               // 0..127
            int j4  = s & 7;                // 0..7
            int n   = n0 + n_l;
            int4 p = *reinterpret_cast<const int4*>(
                packed + (size_t)n * (NUM_GROUPS * 32) + g * 32 + j4 * 4);
            float rcp = 1.0f / __ldg(scale + n * NUM_GROUPS + g);
            float mnv = __ldg(mn + n * NUM_GROUPS + g);
            int pv[4] = {p.x, p.y, p.z, p.w};
#pragma unroll
            for (int bb = 0; bb < 4; bb++) {
                int nib = h ? (pv[bb] & 0xF) : ((pv[bb] >> 4) & 0xF);
                ws[(j4 * 4 + bb) * WS_LD + n_l] = (float)nib * rcp + mnv;
            }
        }
        __syncthreads();

        // ---- compute 8x8 micro-tile over BK=32 ----
#pragma unroll
        for (int k4 = 0; k4 < BK; k4 += 4) {
            float a[TM][4];
#pragma unroll
            for (int i = 0; i < TM; i++) {
                float4 v = *reinterpret_cast<const float4*>(
                    &xs[(ty * TM + i) * XS_LD + k4]);
                a[i][0] = v.x; a[i][1] = v.y; a[i][2] = v.z; a[i][3] = v.w;
            }
#pragma unroll
            for (int kk = 0; kk < 4; kk++) {
                float breg[TN];
#pragma unroll
                for (int j = 0; j < TN; j += 4) {
                    float4 v = *reinterpret_cast<const float4*>(
                        &ws[(k4 + kk) * WS_LD + tx * TN + j]);
                    breg[j + 0] = v.x; breg[j + 1] = v.y;
                    breg[j + 2] = v.z; breg[j + 3] = v.w;
                }
#pragma unroll
                for (int i = 0; i < TM; i++)
#pragma unroll
                    for (int j = 0; j < TN; j++)
                        acc[i][j] += a[i][kk] * breg[j];
            }
        }
        __syncthreads();
    }

    // ---- epilogue: add bias, vectorized stores ----
#pragma unroll
    for (int i = 0; i < TM; i++) {
        size_t m = (size_t)m0 + ty * TM + i;
#pragma unroll
        for (int j = 0; j < TN; j += 4) {
            int n = n0 + tx * TN + j;
            float4 r;
            r.x = acc[i][j + 0] + __ldg(bias + n + 0);
            r.y = acc[i][j + 1] + __ldg(bias + n + 1);
            r.z = acc[i][j + 2] + __ldg(bias + n + 2);
            r.w = acc[i][j + 3] + __ldg(bias + n + 3);
            *reinterpret_cast<float4*>(out + m * N_DIM + n) = r;
        }
    }
}

extern "C" void kernel_launch(void* const* d_in, const int* in_sizes, int n_in,
                              void* d_out, int out_size) {
    const float* x      = (const float*)d_in[0];
    const int*   packed = (const int*)d_in[1];
    const float* mn     = (const float*)d_in[2];
    const float* scale  = (const float*)d_in[3];
    const float* bias   = (const float*)d_in[4];
    float* out = (float*)d_out;

    const int M = in_sizes[0] / K_DIM;       // 8192
    dim3 grid(N_DIM / BN, M / BM);           // (32, 64)
    dim3 block(NTHREADS);
    clinear_kernel<<<grid, block>>>(x, packed, mn, scale, bias, out);
}

// round 4
// speedup vs baseline: 9.0701x; 9.0701x over previous
#include <cuda_runtime.h>
#include <cuda_fp16.h>
#include <cstdint>

// ============================================================================
// CLinear: out[M,N] = x[M,K] @ dequant(W)[N,K]^T + bias
// M=8192, N=4096, K=4096. Base-compute_103-safe: mma.sync fp16 + cp.async.
// ============================================================================

#define K_DIM 4096
#define N_DIM 4096
#define NUM_GROUPS 64
#define M_MAX 8192

#define BM 128
#define BN 128
#define BK 64
#define KT_COUNT (K_DIM / BK)      // 64
#define STAGES 4
#define A_BYTES (BM * BK * 2)      // 16384
#define B_BYTES (BN * BK * 2)      // 16384
#define STAGE_BYTES (A_BYTES + B_BYTES)          // 32768
#define SMEM_TOTAL (STAGES * STAGE_BYTES)        // 131072

// fp16 scratch (device globals: the only legal scratch)
__device__ __half g_xh[(size_t)M_MAX * K_DIM];   // 64 MB
__device__ __half g_wh[(size_t)N_DIM * K_DIM];   // 32 MB

// ---------------------------------------------------------------------------
__device__ __forceinline__ uint32_t smem_u32(const void* p) {
    uint32_t a;
    asm("{ .reg .u64 t; cvta.to.shared.u64 t, %1; cvt.u32.u64 %0, t; }"
        : "=r"(a) : "l"(p));
    return a;
}
// 16B-atom xor swizzle within a 128B row: atom col c (0..7), row r
__device__ __forceinline__ uint32_t swz(uint32_t row, uint32_t c) {
    return row * 128u + ((c ^ (row & 7u)) << 4);
}

#define CP_ASYNC16(dst, src) \
    asm volatile("cp.async.cg.shared.global [%0], [%1], 16;" :: "r"(dst), "l"(src))
#define CP_COMMIT() asm volatile("cp.async.commit_group;")
#define CP_WAIT2()  asm volatile("cp.async.wait_group 2;")

#define LDM_X4(r0, r1, r2, r3, a) \
    asm volatile("ldmatrix.sync.aligned.m8n8.x4.shared.b16 {%0,%1,%2,%3}, [%4];" \
                 : "=r"(r0), "=r"(r1), "=r"(r2), "=r"(r3) : "r"(a))

#define MMA16816(d, a, b)                                                      \
    asm volatile(                                                              \
        "mma.sync.aligned.m16n8k16.row.col.f32.f16.f16.f32 "                   \
        "{%0,%1,%2,%3}, {%4,%5,%6,%7}, {%8,%9}, {%0,%1,%2,%3};"                \
        : "+f"((d)[0]), "+f"((d)[1]), "+f"((d)[2]), "+f"((d)[3])               \
        : "r"((a)[0]), "r"((a)[1]), "r"((a)[2]), "r"((a)[3]),                  \
          "r"((b)[0]), "r"((b)[1]))

// ---------------------------------------------------------------------------
// prep 1: x (f32) -> fp16 scratch. one float4 per thread.
// ---------------------------------------------------------------------------
__global__ void prep_x_kernel(const float* __restrict__ x) {
    size_t f = (size_t)blockIdx.x * blockDim.x + threadIdx.x;   // float4 idx
    float4 v = *reinterpret_cast<const float4*>(x + f * 4);
    __half2 h0 = __floats2half2_rn(v.x, v.y);
    __half2 h1 = __floats2half2_rn(v.z, v.w);
    uint2 o;
    o.x = *reinterpret_cast<uint32_t*>(&h0);
    o.y = *reinterpret_cast<uint32_t*>(&h1);
    *reinterpret_cast<uint2*>(g_xh + f * 4) = o;
}

// ---------------------------------------------------------------------------
// prep 2: dequant packed -> fp16 W[N,K]. one int32 (2 weights) per thread.
// k_hi = g*64 + j, k_lo = g*64 + 32 + j
// ---------------------------------------------------------------------------
__global__ void prep_w_kernel(const int* __restrict__ packed,
                              const float* __restrict__ mn,
                              const float* __restrict__ scale) {
    uint32_t idx = blockIdx.x * blockDim.x + threadIdx.x;
    uint32_t n   = idx >> 11;          // 2048 ints per n row
    uint32_t rem = idx & 2047;
    uint32_t g   = rem >> 5;
    uint32_t j   = rem & 31;
    int p = packed[idx];
    float rcp = 1.0f / scale[n * NUM_GROUPS + g];
    float mv  = mn[n * NUM_GROUPS + g];
    float whi = (float)((p >> 4) & 0xF) * rcp + mv;
    float wlo = (float)(p & 0xF) * rcp + mv;
    size_t base = (size_t)n * K_DIM + g * 64 + j;
    g_wh[base]      = __float2half_rn(whi);
    g_wh[base + 32] = __float2half_rn(wlo);
}

// ---------------------------------------------------------------------------
// GEMM: 256 threads, warp tile 64x32, m16n8k16, 4-stage cp.async pipeline
// ---------------------------------------------------------------------------
__global__ __launch_bounds__(256)
void gemm_kernel(const float* __restrict__ bias, float* __restrict__ out) {
    extern __shared__ char smem[];
    const uint32_t sb = smem_u32(smem);
    const int tid = threadIdx.x;
    const int lane = tid & 31;
    const int wid = tid >> 5;
    const int warp_m = wid & 1;        // 2 warps along M
    const int warp_n = wid >> 1;       // 4 warps along N
    const int m_base = warp_m * 64;
    const int n_base = warp_n * 32;
    const int m0 = blockIdx.y * BM;
    const int n0 = blockIdx.x * BN;

    // per-thread cp.async slots: 4 for A + 4 for B (1024 atoms each tile)
    // atom idx = tid + i*256 ; row = idx>>3, c = idx&7
    const __half* ga[4];
    const __half* gb[4];
    uint32_t sa[4], sbo[4];
#pragma unroll
    for (int i = 0; i < 4; i++) {
        uint32_t idx = tid + i * 256;
        uint32_t r = idx >> 3, c = idx & 7;
        ga[i]  = g_xh + (size_t)(m0 + r) * K_DIM + c * 8;
        gb[i]  = g_wh + (size_t)(n0 + r) * K_DIM + c * 8;
        sa[i]  = swz(r, c);
        sbo[i] = A_BYTES + swz(r, c);
    }

    float acc[4][4][4];
#pragma unroll
    for (int i = 0; i < 4; i++)
#pragma unroll
        for (int j = 0; j < 4; j++)
#pragma unroll
            for (int q = 0; q < 4; q++) acc[i][j][q] = 0.0f;

    // ldmatrix per-thread row components
    const uint32_t a_row = m_base + (lane & 15);       // + i*16
    const uint32_t a_kh  = (lane >> 4) & 1;
    const uint32_t b_row = n_base + (((lane >> 4) & 1) << 3) + (lane & 7); // + jj*16
    const uint32_t b_kh  = (lane >> 3) & 1;

    // ---- prologue: stages 0..2 ----
#pragma unroll
    for (int s = 0; s < STAGES - 1; s++) {
        uint32_t soff = sb + s * STAGE_BYTES;
#pragma unroll
        for (int i = 0; i < 4; i++) {
            CP_ASYNC16(soff + sa[i],  ga[i] + s * BK);
            CP_ASYNC16(soff + sbo[i], gb[i] + s * BK);
        }
        CP_COMMIT();
    }

    for (int kt = 0; kt < KT_COUNT; kt++) {
        CP_WAIT2();
        __syncthreads();

        // prefetch stage kt+3
        {
            int pf = kt + STAGES - 1;
            if (pf < KT_COUNT) {
                uint32_t soff = sb + (pf & (STAGES - 1)) * STAGE_BYTES;
#pragma unroll
                for (int i = 0; i < 4; i++) {
                    CP_ASYNC16(soff + sa[i],  ga[i] + pf * BK);
                    CP_ASYNC16(soff + sbo[i], gb[i] + pf * BK);
                }
            }
            CP_COMMIT();   // empty group when pf >= KT_COUNT keeps wait invariant
        }

        uint32_t As = sb + (kt & (STAGES - 1)) * STAGE_BYTES;
        uint32_t Bs = As + A_BYTES;

#pragma unroll
        for (int ks = 0; ks < 4; ks++) {
            uint32_t afr[4][4];
#pragma unroll
            for (int i = 0; i < 4; i++) {
                uint32_t addr = As + swz(a_row + i * 16, ks * 2 + a_kh);
                LDM_X4(afr[i][0], afr[i][1], afr[i][2], afr[i][3], addr);
            }
            uint32_t bfr[4][2];
#pragma unroll
            for (int jj = 0; jj < 2; jj++) {
                uint32_t addr = Bs + swz(b_row + jj * 16, ks * 2 + b_kh);
                uint32_t r0, r1, r2, r3;
                LDM_X4(r0, r1, r2, r3, addr);
                bfr[jj * 2][0] = r0;  bfr[jj * 2][1] = r1;
                bfr[jj * 2 + 1][0] = r2; bfr[jj * 2 + 1][1] = r3;
            }
#pragma unroll
            for (int i = 0; i < 4; i++)
#pragma unroll
                for (int j = 0; j < 4; j++)
                    MMA16816(acc[i][j], afr[i], bfr[j]);
        }
    }

    // ---- epilogue: bias + stores ----
    const int tq = lane >> 2;          // row within 16
    const int tr = lane & 3;           // col pair
#pragma unroll
    for (int i = 0; i < 4; i++) {
        size_t mrow0 = (size_t)m0 + m_base + i * 16 + tq;
#pragma unroll
        for (int j = 0; j < 4; j++) {
            int ncol = n0 + n_base + j * 8 + tr * 2;
            float2 bv = __ldg(reinterpret_cast<const float2*>(bias + ncol));
            float2 v0 = {acc[i][j][0] + bv.x, acc[i][j][1] + bv.y};
            float2 v1 = {acc[i][j][2] + bv.x, acc[i][j][3] + bv.y};
            *reinterpret_cast<float2*>(out + mrow0 * N_DIM + ncol) = v0;
            *reinterpret_cast<float2*>(out + (mrow0 + 8) * N_DIM + ncol) = v1;
        }
    }
}

// ---------------------------------------------------------------------------
extern "C" void kernel_launch(void* const* d_in, const int* in_sizes, int n_in,
                              void* d_out, int out_size) {
    const float* x      = (const float*)d_in[0];
    const int*   packed = (const int*)d_in[1];
    const float* mn     = (const float*)d_in[2];
    const float* scale  = (const float*)d_in[3];
    const float* bias   = (const float*)d_in[4];
    float* out = (float*)d_out;

    const int M = in_sizes[0] / K_DIM;                 // 8192

    cudaFuncSetAttribute(gemm_kernel,
                         cudaFuncAttributeMaxDynamicSharedMemorySize, SMEM_TOTAL);

    prep_x_kernel<<<(int)(((size_t)M * K_DIM / 4) / 256), 256>>>(x);
    prep_w_kernel<<<(N_DIM * (K_DIM / 64) * 32) / 256, 256>>>(packed, mn, scale);

    dim3 grid(N_DIM / BN, M / BM);                     // (32, 64)
    gemm_kernel<<<grid, 256, SMEM_TOTAL>>>(bias, out);
}

// round 5
// speedup vs baseline: 9.5905x; 1.0574x over previous
#include <cuda_runtime.h>
#include <cuda_fp16.h>
#include <cstdint>

// ============================================================================
// CLinear: out[M,N] = x[M,K] @ dequant(W)[N,K]^T + bias
// M=8192, N=4096, K=4096. Base-compute_103-safe: mma.sync fp16 + cp.async.
// R5: CTA tile 128x256, warp tile 64x64, 4-stage pipeline.
// ============================================================================

#define K_DIM 4096
#define N_DIM 4096
#define NUM_GROUPS 64
#define M_MAX 8192

#define BM 128
#define BN 256
#define BK 64
#define KT_COUNT (K_DIM / BK)      // 64
#define STAGES 4
#define A_BYTES (BM * BK * 2)      // 16384
#define B_BYTES (BN * BK * 2)      // 32768
#define STAGE_BYTES (A_BYTES + B_BYTES)          // 49152
#define SMEM_TOTAL (STAGES * STAGE_BYTES)        // 196608

// fp16 scratch (device globals: the only legal scratch)
__device__ __half g_xh[(size_t)M_MAX * K_DIM];   // 64 MB
__device__ __half g_wh[(size_t)N_DIM * K_DIM];   // 32 MB

// ---------------------------------------------------------------------------
__device__ __forceinline__ uint32_t smem_u32(const void* p) {
    uint32_t a;
    asm("{ .reg .u64 t; cvta.to.shared.u64 t, %1; cvt.u32.u64 %0, t; }"
        : "=r"(a) : "l"(p));
    return a;
}
// 16B-atom xor swizzle within a 128B row: atom col c (0..7), row r
__device__ __forceinline__ uint32_t swz(uint32_t row, uint32_t c) {
    return row * 128u + ((c ^ (row & 7u)) << 4);
}

#define CP_ASYNC16(dst, src) \
    asm volatile("cp.async.cg.shared.global [%0], [%1], 16;" :: "r"(dst), "l"(src))
#define CP_COMMIT() asm volatile("cp.async.commit_group;")
#define CP_WAIT2()  asm volatile("cp.async.wait_group 2;")

#define LDM_X4(r0, r1, r2, r3, a) \
    asm volatile("ldmatrix.sync.aligned.m8n8.x4.shared.b16 {%0,%1,%2,%3}, [%4];" \
                 : "=r"(r0), "=r"(r1), "=r"(r2), "=r"(r3) : "r"(a))

#define MMA16816(d, a, b)                                                      \
    asm volatile(                                                              \
        "mma.sync.aligned.m16n8k16.row.col.f32.f16.f16.f32 "                   \
        "{%0,%1,%2,%3}, {%4,%5,%6,%7}, {%8,%9}, {%0,%1,%2,%3};"                \
        : "+f"((d)[0]), "+f"((d)[1]), "+f"((d)[2]), "+f"((d)[3])               \
        : "r"((a)[0]), "r"((a)[1]), "r"((a)[2]), "r"((a)[3]),                  \
          "r"((b)[0]), "r"((b)[1]))

// ---------------------------------------------------------------------------
// prep 1: x (f32) -> fp16 scratch. one float4 per thread.
// ---------------------------------------------------------------------------
__global__ void prep_x_kernel(const float* __restrict__ x) {
    size_t f = (size_t)blockIdx.x * blockDim.x + threadIdx.x;   // float4 idx
    float4 v = *reinterpret_cast<const float4*>(x + f * 4);
    __half2 h0 = __floats2half2_rn(v.x, v.y);
    __half2 h1 = __floats2half2_rn(v.z, v.w);
    uint2 o;
    o.x = *reinterpret_cast<uint32_t*>(&h0);
    o.y = *reinterpret_cast<uint32_t*>(&h1);
    *reinterpret_cast<uint2*>(g_xh + f * 4) = o;
}

// ---------------------------------------------------------------------------
// prep 2: dequant packed -> fp16 W[N,K]. one int32 (2 weights) per thread.
// ---------------------------------------------------------------------------
__global__ void prep_w_kernel(const int* __restrict__ packed,
                              const float* __restrict__ mn,
                              const float* __restrict__ scale) {
    uint32_t idx = blockIdx.x * blockDim.x + threadIdx.x;
    uint32_t n   = idx >> 11;          // 2048 ints per n row
    uint32_t rem = idx & 2047;
    uint32_t g   = rem >> 5;
    uint32_t j   = rem & 31;
    int p = packed[idx];
    float rcp = 1.0f / scale[n * NUM_GROUPS + g];
    float mv  = mn[n * NUM_GROUPS + g];
    float whi = (float)((p >> 4) & 0xF) * rcp + mv;
    float wlo = (float)(p & 0xF) * rcp + mv;
    size_t base = (size_t)n * K_DIM + g * 64 + j;
    g_wh[base]      = __float2half_rn(whi);
    g_wh[base + 32] = __float2half_rn(wlo);
}

// ---------------------------------------------------------------------------
// GEMM: 256 threads (8 warps), warp tile 64x64, 4-stage cp.async pipeline
// ---------------------------------------------------------------------------
__global__ __launch_bounds__(256, 1)
void gemm_kernel(const float* __restrict__ bias, float* __restrict__ out) {
    extern __shared__ char smem[];
    const uint32_t sb = smem_u32(smem);
    const int tid = threadIdx.x;
    const int lane = tid & 31;
    const int wid = tid >> 5;
    const int warp_m = wid & 1;        // 2 warps along M
    const int warp_n = wid >> 1;       // 4 warps along N
    const int m_base = warp_m * 64;
    const int n_base = warp_n * 64;
    const int m0 = blockIdx.y * BM;
    const int n0 = blockIdx.x * BN;

    // cp.async slots as 32-bit byte offsets from scratch bases
    // A: 1024 atoms -> 4/thread.  B: 2048 atoms -> 8/thread.
    uint32_t ga_off[4], gb_off[8];
    uint32_t sa[4], sbo[8];
#pragma unroll
    for (int i = 0; i < 4; i++) {
        uint32_t idx = tid + i * 256;
        uint32_t r = idx >> 3, c = idx & 7;
        ga_off[i] = ((uint32_t)(m0 + r) * K_DIM + c * 8) * 2;
        sa[i]     = swz(r, c);
    }
#pragma unroll
    for (int i = 0; i < 8; i++) {
        uint32_t idx = tid + i * 256;
        uint32_t r = idx >> 3, c = idx & 7;
        gb_off[i] = ((uint32_t)(n0 + r) * K_DIM + c * 8) * 2;
        sbo[i]    = A_BYTES + swz(r, c);
    }
    const char* gxb = (const char*)g_xh;
    const char* gwb = (const char*)g_wh;

    float acc[4][8][4];
#pragma unroll
    for (int i = 0; i < 4; i++)
#pragma unroll
        for (int j = 0; j < 8; j++)
#pragma unroll
            for (int q = 0; q < 4; q++) acc[i][j][q] = 0.0f;

    // ldmatrix per-thread row components (same mapping as validated R4 kernel)
    const uint32_t a_row = m_base + (lane & 15);       // + i*16
    const uint32_t a_kh  = (lane >> 4) & 1;
    const uint32_t b_row = n_base + (((lane >> 4) & 1) << 3) + (lane & 7); // + jj*16
    const uint32_t b_kh  = (lane >> 3) & 1;

    // ---- prologue: stages 0..2 ----
#pragma unroll
    for (int s = 0; s < STAGES - 1; s++) {
        uint32_t soff = sb + s * STAGE_BYTES;
        uint32_t koff = (uint32_t)s * BK * 2;   // 128 B per kt
#pragma unroll
        for (int i = 0; i < 4; i++)
            CP_ASYNC16(soff + sa[i], gxb + ga_off[i] + koff);
#pragma unroll
        for (int i = 0; i < 8; i++)
            CP_ASYNC16(soff + sbo[i], gwb + gb_off[i] + koff);
        CP_COMMIT();
    }

    for (int kt = 0; kt < KT_COUNT; kt++) {
        CP_WAIT2();
        __syncthreads();

        // prefetch stage kt+3
        {
            int pf = kt + STAGES - 1;
            if (pf < KT_COUNT) {
                uint32_t soff = sb + (pf & (STAGES - 1)) * STAGE_BYTES;
                uint32_t koff = (uint32_t)pf * BK * 2;
#pragma unroll
                for (int i = 0; i < 4; i++)
                    CP_ASYNC16(soff + sa[i], gxb + ga_off[i] + koff);
#pragma unroll
                for (int i = 0; i < 8; i++)
                    CP_ASYNC16(soff + sbo[i], gwb + gb_off[i] + koff);
            }
            CP_COMMIT();   // empty group when done keeps wait invariant
        }

        uint32_t As = sb + (kt & (STAGES - 1)) * STAGE_BYTES;
        uint32_t Bs = As + A_BYTES;

#pragma unroll
        for (int ks = 0; ks < 4; ks++) {
            uint32_t afr[4][4];
#pragma unroll
            for (int i = 0; i < 4; i++) {
                uint32_t addr = As + swz(a_row + i * 16, ks * 2 + a_kh);
                LDM_X4(afr[i][0], afr[i][1], afr[i][2], afr[i][3], addr);
            }
            uint32_t bfr[8][2];
#pragma unroll
            for (int jj = 0; jj < 4; jj++) {
                uint32_t addr = Bs + swz(b_row + jj * 16, ks * 2 + b_kh);
                uint32_t r0, r1, r2, r3;
                LDM_X4(r0, r1, r2, r3, addr);
                bfr[jj * 2][0] = r0;  bfr[jj * 2][1] = r1;
                bfr[jj * 2 + 1][0] = r2; bfr[jj * 2 + 1][1] = r3;
            }
#pragma unroll
            for (int i = 0; i < 4; i++)
#pragma unroll
                for (int j = 0; j < 8; j++)
                    MMA16816(acc[i][j], afr[i], bfr[j]);
        }
    }

    // ---- epilogue: bias + stores ----
    const int tq = lane >> 2;          // row within 16
    const int tr = lane & 3;           // col pair
#pragma unroll
    for (int i = 0; i < 4; i++) {
        size_t mrow0 = (size_t)m0 + m_base + i * 16 + tq;
#pragma unroll
        for (int j = 0; j < 8; j++) {
            int ncol = n0 + n_base + j * 8 + tr * 2;
            float2 bv = __ldg(reinterpret_cast<const float2*>(bias + ncol));
            float2 v0 = {acc[i][j][0] + bv.x, acc[i][j][1] + bv.y};
            float2 v1 = {acc[i][j][2] + bv.x, acc[i][j][3] + bv.y};
            *reinterpret_cast<float2*>(out + mrow0 * N_DIM + ncol) = v0;
            *reinterpret_cast<float2*>(out + (mrow0 + 8) * N_DIM + ncol) = v1;
        }
    }
}

// ---------------------------------------------------------------------------
extern "C" void kernel_launch(void* const* d_in, const int* in_sizes, int n_in,
                              void* d_out, int out_size) {
    const float* x      = (const float*)d_in[0];
    const int*   packed = (const int*)d_in[1];
    const float* mn     = (const float*)d_in[2];
    const float* scale  = (const float*)d_in[3];
    const float* bias   = (const float*)d_in[4];
    float* out = (float*)d_out;

    const int M = in_sizes[0] / K_DIM;                 // 8192

    cudaFuncSetAttribute(gemm_kernel,
                         cudaFuncAttributeMaxDynamicSharedMemorySize, SMEM_TOTAL);

    prep_x_kernel<<<(int)(((size_t)M * K_DIM / 4) / 256), 256>>>(x);
    prep_w_kernel<<<(N_DIM * (K_DIM / 64) * 32) / 256, 256>>>(packed, mn, scale);

    dim3 grid(N_DIM / BN, M / BM);                     // (16, 64)
    gemm_kernel<<<grid, 256, SMEM_TOTAL>>>(bias, out);
}